// round 14
// baseline (speedup 1.0000x reference)
#include <cuda_runtime.h>
#include <cuda_fp16.h>
#include <cstdint>

#define W_IMG 1216
#define H_IMG 352
#define NB    4
#define HW    (H_IMG * W_IMG)
#define CHG   27
#define PT    3
#define NOC   81

#define NREC  264                /* 4 rows x 66 cols */
#define RSTR  140                /* result staging stride (floats): conflict-free */

/* ---- smem: patch (264*128=33792) overlays low end of Rs ---- */
#define SMEM_TOTAL (88 * RSTR * 4)         /* 49280 -> 3 CTAs/SM */

/* B fragments in global, L1-resident: [tk 18][jp 6][lane 32] uint4 */
__device__ uint4 g_wbf4[18 * 6 * 32];
__device__ __half g_offh[(size_t)NB * PT * 18 * HW];
__device__ __half g_affh[(size_t)NB * PT * 9 * HW];
__device__ float g_sink;

__device__ __forceinline__ float h2(float x) {
    return __half2float(__float2half(x));
}
__device__ __forceinline__ uint32_t smem_u32(const void* p) {
    uint32_t a;
    asm("{ .reg .u64 t; cvta.to.shared.u64 t, %1; cvt.u32.u64 %0, t; }"
        : "=r"(a) : "l"(p));
    return a;
}

/* -------- reorder: B fragment pairs, K = tap-major (9 taps x 32 ic) -------- */
__global__ void reorder_kernel(const float* __restrict__ w_off) {
    int i = blockIdx.x * 256 + threadIdx.x;   /* (tk*6 + jp)*32 + lane */
    if (i >= 18 * 6 * 32) return;
    int lane = i & 31;
    int rem  = i >> 5;
    int jp   = rem % 6;
    int tk   = rem / 6;
    int tap  = tk >> 1;
    int ks2  = tk & 1;
    int tg   = lane & 3;
    uint32_t r[4];
#pragma unroll
    for (int s = 0; s < 2; s++) {
        int n = (jp * 2 + s) * 8 + (lane >> 2);
        float v[4];
#pragma unroll
        for (int u = 0; u < 4; u++) {
            int ic = ks2 * 16 + tg * 2 + (u >> 1) * 8 + (u & 1);
            v[u] = (n < NOC && ic < CHG)
                 ? w_off[(size_t)n * 243 + ic * 9 + tap] : 0.f;
        }
        __half2 h0 = __floats2half2_rn(v[0], v[1]);
        __half2 h1 = __floats2half2_rn(v[2], v[3]);
        r[s * 2]     = *(uint32_t*)&h0;
        r[s * 2 + 1] = *(uint32_t*)&h1;
    }
    g_wbf4[i] = make_uint4(r[0], r[1], r[2], r[3]);
}

__global__ void dummy_kernel() { if (threadIdx.x == 0) g_sink = 0.f; }

/* ---------------------------------------------------------------
 * Conv 27->81, implicit GEMM (channel-last swizzled patch, 9 taps),
 * raw mma.sync fp16, B fragments via __ldg. 3 CTAs/SM.
 * CTA = 2 rows x 64 px, 256 threads, warp tile m32 x n48.
 * Patch record: 128 B, halves[ic], 16B-chunk XOR-swizzled by rec&7.
 * --------------------------------------------------------------- */
__global__ void __launch_bounds__(256, 3)
conv_kernel(const float* __restrict__ g,
            const float* __restrict__ b_off,
            float* __restrict__ out_off,
            float* __restrict__ out_aff)
{
    extern __shared__ char smc[];
    float* Rs = (float*)smc;
    const uint32_t smb = smem_u32(smc);

    const int tid  = threadIdx.x;
    const int wid  = tid >> 5;
    const int lane = tid & 31;
    const int x0   = blockIdx.x * 64;
    const int y0   = blockIdx.y * 2;
    const int b    = blockIdx.z;

    /* ---- patch build: warp pass = 8 recs x 4 icg, conflict-free STS.128 ---- */
    {
        const int rl  = lane & 7;
        const int icg = lane >> 3;
        const float* gb = g + (size_t)b * CHG * HW;
        for (int base = wid * 8; base < NREC; base += 64) {
            int rec = base + rl;
            int rr  = rec / 66;
            int c   = rec - rr * 66;
            int gh  = y0 - 1 + rr;
            int gw  = x0 - 1 + c;
            bool ok = ((unsigned)gh < H_IMG) && ((unsigned)gw < W_IMG);
            const float* gp = gb + (size_t)gh * W_IMG + gw;
            uint32_t r[4];
#pragma unroll
            for (int q = 0; q < 4; q++) {
                int ic0 = icg * 8 + q * 2;
                float v0 = (ok && ic0 < CHG)     ? __ldg(gp + (size_t)ic0 * HW) : 0.f;
                float v1 = (ok && ic0 + 1 < CHG) ? __ldg(gp + (size_t)(ic0 + 1) * HW) : 0.f;
                __half2 hv = __floats2half2_rn(v0, v1);
                r[q] = *(uint32_t*)&hv;
            }
            uint32_t addr = smb + ((uint32_t)rec << 7)
                          + (((uint32_t)icg ^ ((uint32_t)rec & 7)) << 4);
            asm volatile("st.shared.v4.b32 [%0], {%1,%2,%3,%4};"
                         :: "r"(addr), "r"(r[0]), "r"(r[1]), "r"(r[2]), "r"(r[3]));
        }
    }
    __syncthreads();

    /* ---- implicit GEMM: warp = m32 x n48, 9 taps x 2 k16 ---- */
    const int mw = wid >> 1;
    const int ng = wid & 1;
    float acc[2][6][4];
#pragma unroll
    for (int i = 0; i < 2; i++)
#pragma unroll
        for (int j = 0; j < 6; j++)
#pragma unroll
            for (int q = 0; q < 4; q++) acc[i][j][q] = 0.f;
    {
        int rec0[2];
#pragma unroll
        for (int i = 0; i < 2; i++) {
            int px = mw * 32 + i * 16 + (lane & 15);
            rec0[i] = (px >> 6) * 66 + (px & 63);
        }
        const uint32_t ch16 = ((uint32_t)(lane >> 4)) << 4;
        const uint4* bp = g_wbf4 + (size_t)ng * 3 * 32 + lane;
#pragma unroll
        for (int tap = 0; tap < 9; tap++) {
            const int trec = (tap / 3) * 66 + (tap % 3);
#pragma unroll
            for (int ks2 = 0; ks2 < 2; ks2++) {
                uint32_t a0[2], a1[2], a2[2], a3[2];
#pragma unroll
                for (int i = 0; i < 2; i++) {
                    uint32_t rec = (uint32_t)(rec0[i] + trec);
                    uint32_t adr = smb + (rec << 7)
                                 + ((((uint32_t)ks2 << 5) + ch16)
                                    ^ ((rec & 7) << 4));
                    asm volatile(
                        "ldmatrix.sync.aligned.m8n8.x4.shared.b16 "
                        "{%0,%1,%2,%3}, [%4];"
                        : "=r"(a0[i]), "=r"(a1[i]), "=r"(a2[i]), "=r"(a3[i])
                        : "r"(adr));
                }
                const uint4* bk = bp + (size_t)(tap * 2 + ks2) * (6 * 32);
#pragma unroll
                for (int jp = 0; jp < 3; jp++) {
                    uint4 bb = __ldg(bk + jp * 32);
#pragma unroll
                    for (int i = 0; i < 2; i++) {
                        asm volatile(
                            "mma.sync.aligned.m16n8k16.row.col.f32.f16.f16.f32 "
                            "{%0,%1,%2,%3}, {%4,%5,%6,%7}, {%8,%9}, {%0,%1,%2,%3};"
                            : "+f"(acc[i][2 * jp][0]), "+f"(acc[i][2 * jp][1]),
                              "+f"(acc[i][2 * jp][2]), "+f"(acc[i][2 * jp][3])
                            : "r"(a0[i]), "r"(a1[i]), "r"(a2[i]), "r"(a3[i]),
                              "r"(bb.x), "r"(bb.y));
                        asm volatile(
                            "mma.sync.aligned.m16n8k16.row.col.f32.f16.f16.f32 "
                            "{%0,%1,%2,%3}, {%4,%5,%6,%7}, {%8,%9}, {%0,%1,%2,%3};"
                            : "+f"(acc[i][2 * jp + 1][0]), "+f"(acc[i][2 * jp + 1][1]),
                              "+f"(acc[i][2 * jp + 1][2]), "+f"(acc[i][2 * jp + 1][3])
                            : "r"(a0[i]), "r"(a1[i]), "r"(a2[i]), "r"(a3[i]),
                              "r"(bb.z), "r"(bb.w));
                    }
                }
            }
        }
    }
    __syncthreads();     /* patch consumed -> Rs may overwrite */

    /* ---- C -> Rs[n][px] (skip n >= 88) ---- */
    {
        const int g8 = lane >> 2;
        const int tg = lane & 3;
#pragma unroll
        for (int i = 0; i < 2; i++) {
            const int px0 = mw * 32 + i * 16 + g8;
#pragma unroll
            for (int j = 0; j < 6; j++) {
                if (ng == 1 && j == 5) continue;   /* n 88..95: pad */
                int n = ng * 48 + j * 8 + tg * 2;
                Rs[n * RSTR + px0]           = acc[i][j][0];
                Rs[(n + 1) * RSTR + px0]     = acc[i][j][1];
                Rs[n * RSTR + px0 + 8]       = acc[i][j][2];
                Rs[(n + 1) * RSTR + px0 + 8] = acc[i][j][3];
            }
        }
    }
    __syncthreads();

    /* ---- epilogue: warps 0-5, t = wid/2, 2 px per thread ---- */
    if (wid < 6) {
        const int t = wid >> 1;
        const int nb = t * CHG;
#pragma unroll
        for (int half = 0; half < 2; half++) {
            const int ppx = (wid & 1) * 64 + half * 32 + lane;
#pragma unroll
            for (int j = 0; j < 18; j++) {
                float v = Rs[(nb + j) * RSTR + ppx] + __ldg(b_off + nb + j);
                Rs[(nb + j) * RSTR + ppx] = h2(v);
            }
            float a[9];
            float m = -1e30f;
#pragma unroll
            for (int j = 0; j < 9; j++) {
                a[j] = Rs[(nb + 18 + j) * RSTR + ppx] + __ldg(b_off + nb + 18 + j);
                m = fmaxf(m, a[j]);
            }
            float s = 0.f;
#pragma unroll
            for (int j = 0; j < 9; j++) { a[j] = __expf(a[j] - m); s += a[j]; }
            float inv = 1.f / s;
#pragma unroll
            for (int j = 0; j < 9; j++)
                Rs[(nb + 18 + j) * RSTR + ppx] = h2(a[j] * inv);
        }
    }
    __syncthreads();

    /* ---- stores: f32 to d_out + fp16 staging ---- */
    for (int idx = tid; idx < NOC * 32; idx += 256) {
        int n  = idx >> 5;
        int gq = idx & 31;
        int rr = gq >> 4;
        int c4 = (gq & 15) << 2;
        float4 v = *(float4*)(Rs + n * RSTR + rr * 64 + c4);
        int t = n / CHG;
        int j = n - t * CHG;
        size_t pix = (size_t)(y0 + rr) * W_IMG + x0 + c4;
        __half2 h0 = __floats2half2_rn(v.x, v.y);
        __half2 h1 = __floats2half2_rn(v.z, v.w);
        if (j < 18) {
            size_t o = ((size_t)(b * PT + t) * 18 + j) * HW + pix;
            *(float4*)(out_off + o) = v;
            *(__half2*)(g_offh + o)     = h0;
            *(__half2*)(g_offh + o + 2) = h1;
        } else {
            size_t o = ((size_t)(b * PT + t) * 9 + (j - 18)) * HW + pix;
            *(float4*)(out_aff + o) = v;
            *(__half2*)(g_affh + o)     = h0;
            *(__half2*)(g_affh + o + 2) = h1;
        }
    }
}

/* ---------------- deformable propagation step ---------------- */
__device__ __forceinline__ float samp(const float* __restrict__ fb, int y, int x) {
    if ((unsigned)y < H_IMG && (unsigned)x < W_IMG) return fb[y * W_IMG + x];
    return 0.f;
}

__global__ void __launch_bounds__(256)
prop_kernel(const float* __restrict__ feat_in,
            const float* __restrict__ confid,
            const float* __restrict__ ffix,
            const float* __restrict__ wf,
            const float* __restrict__ bf,
            float* __restrict__ fout,
            float* __restrict__ fout2,
            int t)
{
    int p = blockIdx.x * 256 + threadIdx.x;
    if (p >= NB * HW) return;
    int b   = p / HW;
    int rem = p - b * HW;
    int h   = rem / W_IMG;
    int w   = rem - h * W_IMG;

    const float* fb = feat_in + (size_t)b * HW;
    const __half* ob = g_offh + (size_t)(b * PT + t) * 18 * HW + rem;
    const __half* ab = g_affh + (size_t)(b * PT + t) * 9 * HW + rem;

    float sum = 0.f;
#pragma unroll
    for (int k = 0; k < 9; k++) {
        float dy = __half2float(ob[(size_t)(2 * k) * HW]);
        float dx = __half2float(ob[(size_t)(2 * k + 1) * HW]);
        float a  = __half2float(ab[(size_t)k * HW]);
        float ys = (float)h + (float)(k / 3 - 1) + dy;
        float xs = (float)w + (float)(k % 3 - 1) + dx;
        float y0 = floorf(ys), x0 = floorf(xs);
        float wy = ys - y0,  wx = xs - x0;
        int y0i = (int)y0, x0i = (int)x0;
        float v00 = samp(fb, y0i,     x0i);
        float v01 = samp(fb, y0i,     x0i + 1);
        float v10 = samp(fb, y0i + 1, x0i);
        float v11 = samp(fb, y0i + 1, x0i + 1);
        float v = v00 * (1.f - wy) * (1.f - wx)
                + v01 * (1.f - wy) * wx
                + v10 * wy * (1.f - wx)
                + v11 * wy * wx;
        sum += v * a * wf[k];
    }
    float prop = sum + bf[0];
    float fx   = ffix[p];
    float sg   = (fx > 0.f) ? 1.f : ((fx < 0.f) ? -1.f : 0.f);
    float conf = sg * (1.f / (1.f + __expf(-confid[p])));
    float o    = (1.f - conf) * prop + conf * fx;
    fout[p] = o;
    if (fout2) fout2[p] = o;
}

/* ------------------------- launch ------------------------- */
extern "C" void kernel_launch(void* const* d_in, const int* in_sizes, int n_in,
                              void* d_out, int out_size)
{
    const float* feat_init  = (const float*)d_in[0];
    const float* guidance   = (const float*)d_in[1];
    const float* confidence = (const float*)d_in[2];
    const float* feat_fix   = (const float*)d_in[3];
    const float* w_off      = (const float*)d_in[4];
    const float* b_off      = (const float*)d_in[5];
    const float* w_f        = (const float*)d_in[6];
    const float* b_f        = (const float*)d_in[7];

    float* out = (float*)d_out;
    const size_t NPIX = (size_t)NB * HW;

    float* out_feat = out;
    float* out_list = out + NPIX;
    float* out_off  = out + 4 * NPIX;
    float* out_aff  = out_off + (size_t)NB * PT * 18 * HW;

    cudaFuncSetAttribute(conv_kernel,
                         cudaFuncAttributeMaxDynamicSharedMemorySize, SMEM_TOTAL);

    /* conv stays MY 4th launch (ncu -s5 lands on it) */
    reorder_kernel<<<(18 * 6 * 32 + 255) / 256, 256>>>(w_off);
    dummy_kernel<<<1, 32>>>();
    dummy_kernel<<<1, 32>>>();

    dim3 cg(W_IMG / 64, H_IMG / 2, NB);
    conv_kernel<<<cg, 256, SMEM_TOTAL>>>(guidance, b_off, out_off, out_aff);

    int np = NB * HW;
    int blocks = (np + 255) / 256;
    prop_kernel<<<blocks, 256>>>(feat_init, confidence, feat_fix, w_f, b_f,
                                 out_list, nullptr, 0);
    prop_kernel<<<blocks, 256>>>(out_list, confidence, feat_fix, w_f, b_f,
                                 out_list + NPIX, nullptr, 1);
    prop_kernel<<<blocks, 256>>>(out_list + NPIX, confidence, feat_fix, w_f, b_f,
                                 out_list + 2 * NPIX, out_feat, 2);
}

// round 16
// speedup vs baseline: 1.0868x; 1.0868x over previous
#include <cuda_runtime.h>
#include <cuda_fp16.h>
#include <cstdint>

#define W_IMG 1216
#define H_IMG 352
#define NB    4
#define HW    (H_IMG * W_IMG)
#define CHG   27
#define PT    3
#define NOC   81

#define RECH  40                 /* 80-byte channel-last record (32 halves + pad) */
#define NREC  264                /* 4 rows x 66 cols */
#define RSTR  140                /* result staging stride (floats): conflict-free */

/* smem: patch (264*80=21120) overlays low end of Rs */
#define SMEM_TOTAL (88 * RSTR * 4)         /* 49280 -> 3 CTAs/SM */

/* B fragments in global, L1-resident: [tk 18][jp 6][lane 32] uint4 */
__device__ uint4 g_wbf4[18 * 6 * 32];
/* fp16 staging: offsets as (dy,dx) half2 pairs, affs planar half */
__device__ __half2 g_offp[(size_t)NB * PT * 9 * HW];
__device__ __half  g_affh[(size_t)NB * PT * 9 * HW];
__device__ float g_sink;

__device__ __forceinline__ float h2(float x) {
    return __half2float(__float2half(x));
}
__device__ __forceinline__ uint32_t smem_u32(const void* p) {
    uint32_t a;
    asm("{ .reg .u64 t; cvta.to.shared.u64 t, %1; cvt.u32.u64 %0, t; }"
        : "=r"(a) : "l"(p));
    return a;
}

/* -------- reorder: B fragment pairs, K = tap-major (9 taps x 32 ic) -------- */
__global__ void reorder_kernel(const float* __restrict__ w_off) {
    int i = blockIdx.x * 256 + threadIdx.x;   /* (tk*6 + jp)*32 + lane */
    if (i >= 18 * 6 * 32) return;
    int lane = i & 31;
    int rem  = i >> 5;
    int jp   = rem % 6;
    int tk   = rem / 6;
    int tap  = tk >> 1;
    int ks2  = tk & 1;
    int tg   = lane & 3;
    uint32_t r[4];
#pragma unroll
    for (int s = 0; s < 2; s++) {
        int n = (jp * 2 + s) * 8 + (lane >> 2);
        float v[4];
#pragma unroll
        for (int u = 0; u < 4; u++) {
            int ic = ks2 * 16 + tg * 2 + (u >> 1) * 8 + (u & 1);
            v[u] = (n < NOC && ic < CHG)
                 ? w_off[(size_t)n * 243 + ic * 9 + tap] : 0.f;
        }
        __half2 h0 = __floats2half2_rn(v[0], v[1]);
        __half2 h1 = __floats2half2_rn(v[2], v[3]);
        r[s * 2]     = *(uint32_t*)&h0;
        r[s * 2 + 1] = *(uint32_t*)&h1;
    }
    g_wbf4[i] = make_uint4(r[0], r[1], r[2], r[3]);
}

__global__ void dummy_kernel() { if (threadIdx.x == 0) g_sink = 0.f; }

/* ---------------------------------------------------------------
 * Conv 27->81, implicit GEMM (channel-last 80B records, 9 taps),
 * raw mma.sync fp16, B fragments via __ldg (uint4). 3 CTAs/SM.
 * CTA = 2 rows x 64 px, 256 threads, warp tile m32 x n48.
 * --------------------------------------------------------------- */
__global__ void __launch_bounds__(256, 3)
conv_kernel(const float* __restrict__ g,
            const float* __restrict__ b_off,
            float* __restrict__ out_off,
            float* __restrict__ out_aff)
{
    extern __shared__ char smc[];
    float* Rs = (float*)smc;
    const uint32_t smb = smem_u32(smc);

    const int tid  = threadIdx.x;
    const int wid  = tid >> 5;
    const int lane = tid & 31;
    const int x0   = blockIdx.x * 64;
    const int y0   = blockIdx.y * 2;
    const int b    = blockIdx.z;

    /* ---- patch build: warp pass = 8 recs x 4 icg, conflict-free STS.128 ---- */
    {
        const int rl  = lane & 7;
        const int icg = lane >> 3;
        const float* gb = g + (size_t)b * CHG * HW;
#pragma unroll
        for (int rowp = 0; rowp < 4; rowp++) {        /* 4 passes x 64 recs + tail */
            int base = rowp * 64 + wid * 8;
            int rec  = base + rl;                     /* covers 0..255 */
            int rr   = rec / 66;
            int c    = rec - rr * 66;
            int gh   = y0 - 1 + rr;
            int gw   = x0 - 1 + c;
            bool ok  = ((unsigned)gh < H_IMG) && ((unsigned)gw < W_IMG);
            const float* gp = gb + (size_t)gh * W_IMG + gw;
            uint32_t r[4];
#pragma unroll
            for (int q = 0; q < 4; q++) {
                int ic0 = icg * 8 + q * 2;
                float v0 = (ok && ic0 < CHG)     ? __ldg(gp + (size_t)ic0 * HW) : 0.f;
                float v1 = (ok && ic0 + 1 < CHG) ? __ldg(gp + (size_t)(ic0 + 1) * HW) : 0.f;
                __half2 hv = __floats2half2_rn(v0, v1);
                r[q] = *(uint32_t*)&hv;
            }
            uint32_t addr = smb + (uint32_t)rec * 80 + ((uint32_t)icg << 4);
            asm volatile("st.shared.v4.b32 [%0], {%1,%2,%3,%4};"
                         :: "r"(addr), "r"(r[0]), "r"(r[1]), "r"(r[2]), "r"(r[3]));
        }
        /* tail recs 256..263 */
        if (tid < 32) {
            int rec = 256 + rl;
            int rr  = rec / 66;
            int c   = rec - rr * 66;
            int gh  = y0 - 1 + rr;
            int gw  = x0 - 1 + c;
            bool ok = ((unsigned)gh < H_IMG) && ((unsigned)gw < W_IMG);
            const float* gp = gb + (size_t)gh * W_IMG + gw;
            uint32_t r[4];
#pragma unroll
            for (int q = 0; q < 4; q++) {
                int ic0 = icg * 8 + q * 2;
                float v0 = (ok && ic0 < CHG)     ? __ldg(gp + (size_t)ic0 * HW) : 0.f;
                float v1 = (ok && ic0 + 1 < CHG) ? __ldg(gp + (size_t)(ic0 + 1) * HW) : 0.f;
                __half2 hv = __floats2half2_rn(v0, v1);
                r[q] = *(uint32_t*)&hv;
            }
            uint32_t addr = smb + (uint32_t)rec * 80 + ((uint32_t)icg << 4);
            asm volatile("st.shared.v4.b32 [%0], {%1,%2,%3,%4};"
                         :: "r"(addr), "r"(r[0]), "r"(r[1]), "r"(r[2]), "r"(r[3]));
        }
    }
    __syncthreads();

    /* ---- implicit GEMM: warp = m32 x n48, 9 taps x 2 k16 ---- */
    const int mw = wid >> 1;
    const int ng = wid & 1;
    float acc[2][6][4];
#pragma unroll
    for (int i = 0; i < 2; i++)
#pragma unroll
        for (int j = 0; j < 6; j++)
#pragma unroll
            for (int q = 0; q < 4; q++) acc[i][j][q] = 0.f;
    {
        uint32_t ab[2];
#pragma unroll
        for (int i = 0; i < 2; i++) {
            int px  = mw * 32 + i * 16 + (lane & 15);
            int rec = (px >> 6) * 66 + (px & 63);
            ab[i] = smb + (uint32_t)rec * 80 + (((uint32_t)(lane >> 4)) << 4);
        }
        const uint4* bp = g_wbf4 + (size_t)ng * 3 * 32 + lane;
#pragma unroll
        for (int tap = 0; tap < 9; tap++) {
            const uint32_t tapd = (uint32_t)((tap / 3) * 66 + (tap % 3)) * 80;
#pragma unroll
            for (int ks2 = 0; ks2 < 2; ks2++) {
                uint32_t a0[2], a1[2], a2[2], a3[2];
#pragma unroll
                for (int i = 0; i < 2; i++)
                    asm volatile(
                        "ldmatrix.sync.aligned.m8n8.x4.shared.b16 "
                        "{%0,%1,%2,%3}, [%4];"
                        : "=r"(a0[i]), "=r"(a1[i]), "=r"(a2[i]), "=r"(a3[i])
                        : "r"(ab[i] + tapd + (uint32_t)ks2 * 32));
                const uint4* bk = bp + (size_t)(tap * 2 + ks2) * (6 * 32);
#pragma unroll
                for (int jp = 0; jp < 3; jp++) {
                    uint4 bb = __ldg(bk + jp * 32);
#pragma unroll
                    for (int i = 0; i < 2; i++) {
                        asm volatile(
                            "mma.sync.aligned.m16n8k16.row.col.f32.f16.f16.f32 "
                            "{%0,%1,%2,%3}, {%4,%5,%6,%7}, {%8,%9}, {%0,%1,%2,%3};"
                            : "+f"(acc[i][2 * jp][0]), "+f"(acc[i][2 * jp][1]),
                              "+f"(acc[i][2 * jp][2]), "+f"(acc[i][2 * jp][3])
                            : "r"(a0[i]), "r"(a1[i]), "r"(a2[i]), "r"(a3[i]),
                              "r"(bb.x), "r"(bb.y));
                        asm volatile(
                            "mma.sync.aligned.m16n8k16.row.col.f32.f16.f16.f32 "
                            "{%0,%1,%2,%3}, {%4,%5,%6,%7}, {%8,%9}, {%0,%1,%2,%3};"
                            : "+f"(acc[i][2 * jp + 1][0]), "+f"(acc[i][2 * jp + 1][1]),
                              "+f"(acc[i][2 * jp + 1][2]), "+f"(acc[i][2 * jp + 1][3])
                            : "r"(a0[i]), "r"(a1[i]), "r"(a2[i]), "r"(a3[i]),
                              "r"(bb.z), "r"(bb.w));
                    }
                }
            }
        }
    }
    __syncthreads();     /* patch consumed -> Rs may overwrite */

    /* ---- C -> Rs[n][px] (skip n >= 88) ---- */
    {
        const int g8 = lane >> 2;
        const int tg = lane & 3;
#pragma unroll
        for (int i = 0; i < 2; i++) {
            const int px0 = mw * 32 + i * 16 + g8;
#pragma unroll
            for (int j = 0; j < 6; j++) {
                if (ng == 1 && j == 5) continue;   /* n 88..95: pad */
                int n = ng * 48 + j * 8 + tg * 2;
                Rs[n * RSTR + px0]           = acc[i][j][0];
                Rs[(n + 1) * RSTR + px0]     = acc[i][j][1];
                Rs[n * RSTR + px0 + 8]       = acc[i][j][2];
                Rs[(n + 1) * RSTR + px0 + 8] = acc[i][j][3];
            }
        }
    }
    __syncthreads();

    /* ---- epilogue: all 8 warps, 384 (t,px) tasks ---- */
    for (int task = tid; task < PT * 128; task += 256) {
        const int t   = task >> 7;
        const int ppx = task & 127;
        const int nb  = t * CHG;
#pragma unroll
        for (int j = 0; j < 18; j++) {
            float v = Rs[(nb + j) * RSTR + ppx] + __ldg(b_off + nb + j);
            Rs[(nb + j) * RSTR + ppx] = h2(v);
        }
        float a[9];
        float m = -1e30f;
#pragma unroll
        for (int j = 0; j < 9; j++) {
            a[j] = Rs[(nb + 18 + j) * RSTR + ppx] + __ldg(b_off + nb + 18 + j);
            m = fmaxf(m, a[j]);
        }
        float s = 0.f;
#pragma unroll
        for (int j = 0; j < 9; j++) { a[j] = __expf(a[j] - m); s += a[j]; }
        float inv = 1.f / s;
#pragma unroll
        for (int j = 0; j < 9; j++)
            Rs[(nb + 18 + j) * RSTR + ppx] = h2(a[j] * inv);
    }
    __syncthreads();

    /* ---- stores: f32 to d_out (+ affs fp16 staging) ---- */
    for (int idx = tid; idx < NOC * 32; idx += 256) {
        int n  = idx >> 5;
        int gq = idx & 31;
        int rr = gq >> 4;
        int c4 = (gq & 15) << 2;
        float4 v = *(float4*)(Rs + n * RSTR + rr * 64 + c4);
        int t = n / CHG;
        int j = n - t * CHG;
        size_t pix = (size_t)(y0 + rr) * W_IMG + x0 + c4;
        if (j < 18) {
            *(float4*)(out_off + ((size_t)(b * PT + t) * 18 + j) * HW + pix) = v;
        } else {
            size_t o = ((size_t)(b * PT + t) * 9 + (j - 18)) * HW + pix;
            *(float4*)(out_aff + o) = v;
            __half2 h0 = __floats2half2_rn(v.x, v.y);
            __half2 h1 = __floats2half2_rn(v.z, v.w);
            *(__half2*)(g_affh + o)     = h0;
            *(__half2*)(g_affh + o + 2) = h1;
        }
    }
    /* ---- offset (dy,dx) half2 pair staging: 27 planes x 32 quads ---- */
    for (int idx = tid; idx < PT * 9 * 32; idx += 256) {
        int k  = idx >> 5;            /* 0..26 */
        int gq = idx & 31;
        int rr = gq >> 4;
        int c4 = (gq & 15) << 2;
        int t  = k / 9;
        int kk = k - t * 9;
        int n0 = t * CHG + 2 * kk;
        const float* ry = Rs + n0 * RSTR + rr * 64 + c4;
        const float* rx = Rs + (n0 + 1) * RSTR + rr * 64 + c4;
        size_t pix = (size_t)(y0 + rr) * W_IMG + x0 + c4;
        __half2* dst = g_offp + ((size_t)(b * PT + t) * 9 + kk) * HW + pix;
#pragma unroll
        for (int u = 0; u < 4; u++)
            dst[u] = __floats2half2_rn(ry[u], rx[u]);
    }
}

/* ---------------- deformable propagation step ---------------- */
__device__ __forceinline__ float samp(const float* __restrict__ fb, int y, int x) {
    if ((unsigned)y < H_IMG && (unsigned)x < W_IMG) return fb[y * W_IMG + x];
    return 0.f;
}

__global__ void __launch_bounds__(256)
prop_kernel(const float* __restrict__ feat_in,
            const float* __restrict__ confid,
            const float* __restrict__ ffix,
            const float* __restrict__ wf,
            const float* __restrict__ bf,
            float* __restrict__ fout,
            float* __restrict__ fout2,
            int t)
{
    int p = blockIdx.x * 256 + threadIdx.x;
    if (p >= NB * HW) return;
    int b   = p / HW;
    int rem = p - b * HW;
    int h   = rem / W_IMG;
    int w   = rem - h * W_IMG;

    const float* fb = feat_in + (size_t)b * HW;
    const __half2* op = g_offp + (size_t)(b * PT + t) * 9 * HW + rem;
    const __half*  ab = g_affh + (size_t)(b * PT + t) * 9 * HW + rem;

    float sum = 0.f;
#pragma unroll
    for (int k = 0; k < 9; k++) {
        __half2 od = __ldg(op + (size_t)k * HW);
        float dy = __half2float(__low2half(od));
        float dx = __half2float(__high2half(od));
        float a  = __half2float(__ldg(ab + (size_t)k * HW));
        float ys = (float)h + (float)(k / 3 - 1) + dy;
        float xs = (float)w + (float)(k % 3 - 1) + dx;
        float y0 = floorf(ys), x0 = floorf(xs);
        float wy = ys - y0,  wx = xs - x0;
        int y0i = (int)y0, x0i = (int)x0;
        float v00 = samp(fb, y0i,     x0i);
        float v01 = samp(fb, y0i,     x0i + 1);
        float v10 = samp(fb, y0i + 1, x0i);
        float v11 = samp(fb, y0i + 1, x0i + 1);
        float v = v00 * (1.f - wy) * (1.f - wx)
                + v01 * (1.f - wy) * wx
                + v10 * wy * (1.f - wx)
                + v11 * wy * wx;
        sum += v * a * wf[k];
    }
    float prop = sum + bf[0];
    float fx   = ffix[p];
    float sg   = (fx > 0.f) ? 1.f : ((fx < 0.f) ? -1.f : 0.f);
    float conf = sg * (1.f / (1.f + __expf(-confid[p])));
    float o    = (1.f - conf) * prop + conf * fx;
    fout[p] = o;
    if (fout2) fout2[p] = o;
}

/* ------------------------- launch ------------------------- */
extern "C" void kernel_launch(void* const* d_in, const int* in_sizes, int n_in,
                              void* d_out, int out_size)
{
    const float* feat_init  = (const float*)d_in[0];
    const float* guidance   = (const float*)d_in[1];
    const float* confidence = (const float*)d_in[2];
    const float* feat_fix   = (const float*)d_in[3];
    const float* w_off      = (const float*)d_in[4];
    const float* b_off      = (const float*)d_in[5];
    const float* w_f        = (const float*)d_in[6];
    const float* b_f        = (const float*)d_in[7];

    float* out = (float*)d_out;
    const size_t NPIX = (size_t)NB * HW;

    float* out_feat = out;
    float* out_list = out + NPIX;
    float* out_off  = out + 4 * NPIX;
    float* out_aff  = out_off + (size_t)NB * PT * 18 * HW;

    cudaFuncSetAttribute(conv_kernel,
                         cudaFuncAttributeMaxDynamicSharedMemorySize, SMEM_TOTAL);

    /* conv stays MY 4th launch (ncu -s5 lands on it) */
    reorder_kernel<<<(18 * 6 * 32 + 255) / 256, 256>>>(w_off);
    dummy_kernel<<<1, 32>>>();
    dummy_kernel<<<1, 32>>>();

    dim3 cg(W_IMG / 64, H_IMG / 2, NB);
    conv_kernel<<<cg, 256, SMEM_TOTAL>>>(guidance, b_off, out_off, out_aff);

    int np = NB * HW;
    int blocks = (np + 255) / 256;
    prop_kernel<<<blocks, 256>>>(feat_init, confidence, feat_fix, w_f, b_f,
                                 out_list, nullptr, 0);
    prop_kernel<<<blocks, 256>>>(out_list, confidence, feat_fix, w_f, b_f,
                                 out_list + NPIX, nullptr, 1);
    prop_kernel<<<blocks, 256>>>(out_list + NPIX, confidence, feat_fix, w_f, b_f,
                                 out_list + 2 * NPIX, out_feat, 2);
}

// round 17
// speedup vs baseline: 1.3138x; 1.2088x over previous
#include <cuda_runtime.h>
#include <cuda_fp16.h>
#include <cstdint>

#define W_IMG 1216
#define H_IMG 352
#define NB    4
#define HW    (H_IMG * W_IMG)
#define CHG   27
#define PT    3
#define NOC   81

#define NREC  264                /* 4 rows x 66 cols */
#define RSTR  140                /* result staging stride (floats): conflict-free */

/* smem: patch (264*80=21120) overlays low end of Rs */
#define SMEM_TOTAL (88 * RSTR * 4)         /* 49280 -> 3 CTAs/SM */

/* B fragments in global, L1-resident: [tk 18][jp 6][lane 32] uint4 */
__device__ uint4 g_wbf4[18 * 6 * 32];
/* fp16 staging: offsets as (dy,dx) half2 pairs, affs planar half */
__device__ __half2 g_offp[(size_t)NB * PT * 9 * HW];
__device__ __half  g_affh[(size_t)NB * PT * 9 * HW];
__device__ float g_sink;

__device__ __forceinline__ float h2(float x) {
    return __half2float(__float2half(x));
}
__device__ __forceinline__ uint32_t smem_u32(const void* p) {
    uint32_t a;
    asm("{ .reg .u64 t; cvta.to.shared.u64 t, %1; cvt.u32.u64 %0, t; }"
        : "=r"(a) : "l"(p));
    return a;
}

/* -------- reorder: B fragment pairs, K = tap-major (9 taps x 32 ic) -------- */
__global__ void reorder_kernel(const float* __restrict__ w_off) {
    int i = blockIdx.x * 256 + threadIdx.x;   /* (tk*6 + jp)*32 + lane */
    if (i >= 18 * 6 * 32) return;
    int lane = i & 31;
    int rem  = i >> 5;
    int jp   = rem % 6;
    int tk   = rem / 6;
    int tap  = tk >> 1;
    int ks2  = tk & 1;
    int tg   = lane & 3;
    uint32_t r[4];
#pragma unroll
    for (int s = 0; s < 2; s++) {
        int n = (jp * 2 + s) * 8 + (lane >> 2);
        float v[4];
#pragma unroll
        for (int u = 0; u < 4; u++) {
            int ic = ks2 * 16 + tg * 2 + (u >> 1) * 8 + (u & 1);
            v[u] = (n < NOC && ic < CHG)
                 ? w_off[(size_t)n * 243 + ic * 9 + tap] : 0.f;
        }
        __half2 h0 = __floats2half2_rn(v[0], v[1]);
        __half2 h1 = __floats2half2_rn(v[2], v[3]);
        r[s * 2]     = *(uint32_t*)&h0;
        r[s * 2 + 1] = *(uint32_t*)&h1;
    }
    g_wbf4[i] = make_uint4(r[0], r[1], r[2], r[3]);
}

__global__ void dummy_kernel() { if (threadIdx.x == 0) g_sink = 0.f; }

/* ---------------------------------------------------------------
 * Conv 27->81, implicit GEMM (channel-last 80B records, 9 taps),
 * raw mma.sync fp16, B fragments via __ldg (uint4). 3 CTAs/SM.
 * CTA = 2 rows x 64 px, 256 threads, warp tile m32 x n48/n40.
 * Fused epilogue: bias + fp16-round + softmax straight to gmem.
 * --------------------------------------------------------------- */
__global__ void __launch_bounds__(256, 3)
conv_kernel(const float* __restrict__ g,
            const float* __restrict__ b_off,
            float* __restrict__ out_off,
            float* __restrict__ out_aff)
{
    extern __shared__ char smc[];
    float* Rs = (float*)smc;
    const uint32_t smb = smem_u32(smc);

    const int tid  = threadIdx.x;
    const int wid  = tid >> 5;
    const int lane = tid & 31;
    const int x0   = blockIdx.x * 64;
    const int y0   = blockIdx.y * 2;
    const int b    = blockIdx.z;

    /* ---- patch build: warp pass = 8 recs x 4 icg, conflict-free STS.128 ---- */
    {
        const int rl  = lane & 7;
        const int icg = lane >> 3;
        const float* gb = g + (size_t)b * CHG * HW;
#pragma unroll
        for (int rowp = 0; rowp < 4; rowp++) {
            int rec  = rowp * 64 + wid * 8 + rl;
            int rr   = rec / 66;
            int c    = rec - rr * 66;
            int gh   = y0 - 1 + rr;
            int gw   = x0 - 1 + c;
            bool ok  = ((unsigned)gh < H_IMG) && ((unsigned)gw < W_IMG);
            const float* gp = gb + (size_t)gh * W_IMG + gw;
            uint32_t r[4];
#pragma unroll
            for (int q = 0; q < 4; q++) {
                int ic0 = icg * 8 + q * 2;
                float v0 = (ok && ic0 < CHG)     ? __ldg(gp + (size_t)ic0 * HW) : 0.f;
                float v1 = (ok && ic0 + 1 < CHG) ? __ldg(gp + (size_t)(ic0 + 1) * HW) : 0.f;
                __half2 hv = __floats2half2_rn(v0, v1);
                r[q] = *(uint32_t*)&hv;
            }
            uint32_t addr = smb + (uint32_t)rec * 80 + ((uint32_t)icg << 4);
            asm volatile("st.shared.v4.b32 [%0], {%1,%2,%3,%4};"
                         :: "r"(addr), "r"(r[0]), "r"(r[1]), "r"(r[2]), "r"(r[3]));
        }
        if (tid < 32) {   /* tail recs 256..263 */
            int rec = 256 + rl;
            int rr  = rec / 66;
            int c   = rec - rr * 66;
            int gh  = y0 - 1 + rr;
            int gw  = x0 - 1 + c;
            bool ok = ((unsigned)gh < H_IMG) && ((unsigned)gw < W_IMG);
            const float* gp = gb + (size_t)gh * W_IMG + gw;
            uint32_t r[4];
#pragma unroll
            for (int q = 0; q < 4; q++) {
                int ic0 = icg * 8 + q * 2;
                float v0 = (ok && ic0 < CHG)     ? __ldg(gp + (size_t)ic0 * HW) : 0.f;
                float v1 = (ok && ic0 + 1 < CHG) ? __ldg(gp + (size_t)(ic0 + 1) * HW) : 0.f;
                __half2 hv = __floats2half2_rn(v0, v1);
                r[q] = *(uint32_t*)&hv;
            }
            uint32_t addr = smb + (uint32_t)rec * 80 + ((uint32_t)icg << 4);
            asm volatile("st.shared.v4.b32 [%0], {%1,%2,%3,%4};"
                         :: "r"(addr), "r"(r[0]), "r"(r[1]), "r"(r[2]), "r"(r[3]));
        }
    }
    __syncthreads();

    /* ---- implicit GEMM: warp = m32 x n48 (ng0) / n40 (ng1) ---- */
    const int mw = wid >> 1;
    const int ng = wid & 1;
    float acc[2][6][4];
#pragma unroll
    for (int i = 0; i < 2; i++)
#pragma unroll
        for (int j = 0; j < 6; j++)
#pragma unroll
            for (int q = 0; q < 4; q++) acc[i][j][q] = 0.f;
    {
        uint32_t ab[2];
#pragma unroll
        for (int i = 0; i < 2; i++) {
            int px  = mw * 32 + i * 16 + (lane & 15);
            int rec = (px >> 6) * 66 + (px & 63);
            ab[i] = smb + (uint32_t)rec * 80 + (((uint32_t)(lane >> 4)) << 4);
        }
        const uint4* bp = g_wbf4 + (size_t)ng * 3 * 32 + lane;
#pragma unroll
        for (int tap = 0; tap < 9; tap++) {
            const uint32_t tapd = (uint32_t)((tap / 3) * 66 + (tap % 3)) * 80;
#pragma unroll
            for (int ks2 = 0; ks2 < 2; ks2++) {
                uint32_t a0[2], a1[2], a2[2], a3[2];
#pragma unroll
                for (int i = 0; i < 2; i++)
                    asm volatile(
                        "ldmatrix.sync.aligned.m8n8.x4.shared.b16 "
                        "{%0,%1,%2,%3}, [%4];"
                        : "=r"(a0[i]), "=r"(a1[i]), "=r"(a2[i]), "=r"(a3[i])
                        : "r"(ab[i] + tapd + (uint32_t)ks2 * 32));
                const uint4* bk = bp + (size_t)(tap * 2 + ks2) * (6 * 32);
#pragma unroll
                for (int jp = 0; jp < 3; jp++) {
                    uint4 bb = __ldg(bk + jp * 32);
#pragma unroll
                    for (int i = 0; i < 2; i++) {
                        asm volatile(
                            "mma.sync.aligned.m16n8k16.row.col.f32.f16.f16.f32 "
                            "{%0,%1,%2,%3}, {%4,%5,%6,%7}, {%8,%9}, {%0,%1,%2,%3};"
                            : "+f"(acc[i][2 * jp][0]), "+f"(acc[i][2 * jp][1]),
                              "+f"(acc[i][2 * jp][2]), "+f"(acc[i][2 * jp][3])
                            : "r"(a0[i]), "r"(a1[i]), "r"(a2[i]), "r"(a3[i]),
                              "r"(bb.x), "r"(bb.y));
                        if (!(ng == 1 && jp == 2))   /* skip pad n 88..95 */
                            asm volatile(
                                "mma.sync.aligned.m16n8k16.row.col.f32.f16.f16.f32 "
                                "{%0,%1,%2,%3}, {%4,%5,%6,%7}, {%8,%9}, {%0,%1,%2,%3};"
                                : "+f"(acc[i][2 * jp + 1][0]), "+f"(acc[i][2 * jp + 1][1]),
                                  "+f"(acc[i][2 * jp + 1][2]), "+f"(acc[i][2 * jp + 1][3])
                                : "r"(a0[i]), "r"(a1[i]), "r"(a2[i]), "r"(a3[i]),
                                  "r"(bb.z), "r"(bb.w));
                    }
                }
            }
        }
    }
    __syncthreads();     /* patch consumed -> Rs may overwrite */

    /* ---- C -> Rs[n][px] (skip n >= 88) ---- */
    {
        const int g8 = lane >> 2;
        const int tg = lane & 3;
#pragma unroll
        for (int i = 0; i < 2; i++) {
            const int px0 = mw * 32 + i * 16 + g8;
#pragma unroll
            for (int j = 0; j < 6; j++) {
                if (ng == 1 && j == 5) continue;
                int n = ng * 48 + j * 8 + tg * 2;
                Rs[n * RSTR + px0]           = acc[i][j][0];
                Rs[(n + 1) * RSTR + px0]     = acc[i][j][1];
                Rs[n * RSTR + px0 + 8]       = acc[i][j][2];
                Rs[(n + 1) * RSTR + px0 + 8] = acc[i][j][3];
            }
        }
    }
    __syncthreads();

    /* ---- fused epilogue: bias + fp16 round + softmax -> gmem ---- */
    for (int task = tid; task < PT * 128; task += 256) {
        const int t   = task >> 7;
        const int ppx = task & 127;
        const int rr  = ppx >> 6;
        const int cc  = ppx & 63;
        const size_t pix = (size_t)(y0 + rr) * W_IMG + x0 + cc;
        const int nb  = t * CHG;
        float v[27];
#pragma unroll
        for (int j = 0; j < 27; j++)
            v[j] = Rs[(nb + j) * RSTR + ppx] + __ldg(b_off + nb + j);

        float* ob = out_off + (size_t)(b * PT + t) * 18 * HW + pix;
#pragma unroll
        for (int j = 0; j < 18; j++)
            ob[(size_t)j * HW] = h2(v[j]);

        __half2* odst = g_offp + (size_t)(b * PT + t) * 9 * HW + pix;
#pragma unroll
        for (int k = 0; k < 9; k++)
            odst[(size_t)k * HW] = __floats2half2_rn(v[2 * k], v[2 * k + 1]);

        float m = v[18];
#pragma unroll
        for (int j = 19; j < 27; j++) m = fmaxf(m, v[j]);
        float e[9], s = 0.f;
#pragma unroll
        for (int j = 0; j < 9; j++) { e[j] = __expf(v[18 + j] - m); s += e[j]; }
        float inv = 1.f / s;
        float* ap = out_aff + (size_t)(b * PT + t) * 9 * HW + pix;
        __half* adst = g_affh + (size_t)(b * PT + t) * 9 * HW + pix;
#pragma unroll
        for (int j = 0; j < 9; j++) {
            float r = e[j] * inv;
            ap[(size_t)j * HW]   = h2(r);
            adst[(size_t)j * HW] = __float2half(r);
        }
    }
}

/* ---------------- deformable propagation step (2 px/thread) ---------------- */
__device__ __forceinline__ float samp(const float* __restrict__ fb, int y, int x) {
    if ((unsigned)y < H_IMG && (unsigned)x < W_IMG) return fb[y * W_IMG + x];
    return 0.f;
}

__global__ void __launch_bounds__(256)
prop_kernel(const float* __restrict__ feat_in,
            const float* __restrict__ confid,
            const float* __restrict__ ffix,
            const float* __restrict__ wf,
            const float* __restrict__ bf,
            float* __restrict__ fout,
            float* __restrict__ fout2,
            int t)
{
    int p2 = blockIdx.x * 256 + threadIdx.x;
    if (p2 >= NB * HW / 2) return;
    int p   = 2 * p2;
    int b   = p / HW;
    int rem = p - b * HW;
    int h   = rem / W_IMG;
    int w   = rem - h * W_IMG;

    const float* fb = feat_in + (size_t)b * HW;
    const __half2* op = g_offp + (size_t)(b * PT + t) * 9 * HW + rem;
    const __half*  ab = g_affh + (size_t)(b * PT + t) * 9 * HW + rem;

    float sum0 = 0.f, sum1 = 0.f;
#pragma unroll
    for (int k = 0; k < 9; k++) {
        uint2 odb = __ldg((const uint2*)(op + (size_t)k * HW));
        __half2 od0 = *(__half2*)&odb.x;
        __half2 od1 = *(__half2*)&odb.y;
        __half2 a2  = __ldg((const __half2*)(ab + (size_t)k * HW));
        float wk = __ldg(wf + k);
        const float bdy = (float)(k / 3 - 1);
        const float bdx = (float)(k % 3 - 1);
        /* px 0 */
        {
            float ys = (float)h + bdy + __half2float(__low2half(od0));
            float xs = (float)w + bdx + __half2float(__high2half(od0));
            float y0f = floorf(ys), x0f = floorf(xs);
            float wy = ys - y0f, wx = xs - x0f;
            int y0i = (int)y0f, x0i = (int)x0f;
            float v00 = samp(fb, y0i,     x0i);
            float v01 = samp(fb, y0i,     x0i + 1);
            float v10 = samp(fb, y0i + 1, x0i);
            float v11 = samp(fb, y0i + 1, x0i + 1);
            float v = v00 * (1.f - wy) * (1.f - wx) + v01 * (1.f - wy) * wx
                    + v10 * wy * (1.f - wx)         + v11 * wy * wx;
            sum0 += v * __half2float(__low2half(a2)) * wk;
        }
        /* px 1 */
        {
            float ys = (float)h + bdy + __half2float(__low2half(od1));
            float xs = (float)(w + 1) + bdx + __half2float(__high2half(od1));
            float y0f = floorf(ys), x0f = floorf(xs);
            float wy = ys - y0f, wx = xs - x0f;
            int y0i = (int)y0f, x0i = (int)x0f;
            float v00 = samp(fb, y0i,     x0i);
            float v01 = samp(fb, y0i,     x0i + 1);
            float v10 = samp(fb, y0i + 1, x0i);
            float v11 = samp(fb, y0i + 1, x0i + 1);
            float v = v00 * (1.f - wy) * (1.f - wx) + v01 * (1.f - wy) * wx
                    + v10 * wy * (1.f - wx)         + v11 * wy * wx;
            sum1 += v * __half2float(__high2half(a2)) * wk;
        }
    }
    float bias = __ldg(bf);
    float2 cf2 = *(const float2*)(confid + p);
    float2 fx2 = *(const float2*)(ffix + p);
    float o0, o1;
    {
        float fx = fx2.x;
        float sg = (fx > 0.f) ? 1.f : ((fx < 0.f) ? -1.f : 0.f);
        float conf = sg * (1.f / (1.f + __expf(-cf2.x)));
        o0 = (1.f - conf) * (sum0 + bias) + conf * fx;
    }
    {
        float fx = fx2.y;
        float sg = (fx > 0.f) ? 1.f : ((fx < 0.f) ? -1.f : 0.f);
        float conf = sg * (1.f / (1.f + __expf(-cf2.y)));
        o1 = (1.f - conf) * (sum1 + bias) + conf * fx;
    }
    *(float2*)(fout + p) = make_float2(o0, o1);
    if (fout2) *(float2*)(fout2 + p) = make_float2(o0, o1);
}

/* ------------------------- launch ------------------------- */
extern "C" void kernel_launch(void* const* d_in, const int* in_sizes, int n_in,
                              void* d_out, int out_size)
{
    const float* feat_init  = (const float*)d_in[0];
    const float* guidance   = (const float*)d_in[1];
    const float* confidence = (const float*)d_in[2];
    const float* feat_fix   = (const float*)d_in[3];
    const float* w_off      = (const float*)d_in[4];
    const float* b_off      = (const float*)d_in[5];
    const float* w_f        = (const float*)d_in[6];
    const float* b_f        = (const float*)d_in[7];

    float* out = (float*)d_out;
    const size_t NPIX = (size_t)NB * HW;

    float* out_feat = out;
    float* out_list = out + NPIX;
    float* out_off  = out + 4 * NPIX;
    float* out_aff  = out_off + (size_t)NB * PT * 18 * HW;

    cudaFuncSetAttribute(conv_kernel,
                         cudaFuncAttributeMaxDynamicSharedMemorySize, SMEM_TOTAL);

    /* conv stays MY 4th launch (ncu -s5 lands on it) */
    reorder_kernel<<<(18 * 6 * 32 + 255) / 256, 256>>>(w_off);
    dummy_kernel<<<1, 32>>>();
    dummy_kernel<<<1, 32>>>();

    dim3 cg(W_IMG / 64, H_IMG / 2, NB);
    conv_kernel<<<cg, 256, SMEM_TOTAL>>>(guidance, b_off, out_off, out_aff);

    int np2 = NB * HW / 2;
    int blocks = (np2 + 255) / 256;
    prop_kernel<<<blocks, 256>>>(feat_init, confidence, feat_fix, w_f, b_f,
                                 out_list, nullptr, 0);
    prop_kernel<<<blocks, 256>>>(out_list, confidence, feat_fix, w_f, b_f,
                                 out_list + NPIX, nullptr, 1);
    prop_kernel<<<blocks, 256>>>(out_list + NPIX, confidence, feat_fix, w_f, b_f,
                                 out_list + 2 * NPIX, out_feat, 2);
}